// round 16
// baseline (speedup 1.0000x reference)
#include <cuda_runtime.h>

#define NROWS  512
#define DDIM   512
#define RT     128          // tile rows
#define CT     64           // tile cols
#define NTILES 20           // upper-tri tiles: bm 0..3 (128-row), bn>=2bm (64-col)
#define KSPLIT 7            // k-slices {72,72,72,72,72,72,80}
#define GRID   (NTILES * KSPLIT)   // 140 blocks < 148 SMs -> co-resident, spin-safe

typedef unsigned long long ull;

// Packed-f32x2 FMA: d = a*b + c elementwise on (lo,hi) float pairs.
#define FMA_F32X2(d, a, b, c) \
    asm("fma.rn.f32x2 %0, %1, %2, %3;" : "=l"(d) : "l"(a), "l"(b), "l"(c))

// Scratch (allocation-free rule: __device__ globals)
__device__ float g_part[KSPLIT * NROWS * NROWS];  // k-split partial dots
__device__ float g_diag[KSPLIT][NROWS];           // k-split partial diagonal
__device__ int   g_bar  = 0;                      // phase barrier (reset each call)
__device__ int   g_done = 0;                      // completion counter (reset each call)

// ---------------------------------------------------------------------------
// Fused kernel: k-packed FFMA2 GEMM (phase 1) + spin barrier + triplet (phase 2).
// 140 blocks x 256 threads, 1/SM co-resident.
//
// Phase 1: 128x64 tiles, 8x4 micro-tile, K packed in pairs: smem holds
// float4 = (m0k0,m0k1,m1k0,m1k1); inner step = 6x LDS.128 + 32x FFMA2
// (96 B smem per 64 FMA). Accumulators are packed f32x2 (both k-parities),
// unpacked once in the epilogue. Two staged chunks per k-slice.
//
// Phase 2: 512 anchor-slots over 140 blocks (slot = bid + 140*w, w<4,
// anchor = slot*293 & 511). 7-partial sums, uniform ballot compaction,
// np x 16 register fmax hot loop, one atomicAdd per block.
// ---------------------------------------------------------------------------
__global__ void __launch_bounds__(256, 1)
fused_kernel(const float* __restrict__ embs,
             const void* __restrict__ idxraw,
             float* __restrict__ out) {
    const int tid = threadIdx.x;          // 0..255
    const int bid = blockIdx.x;

    __shared__ float4 As4[20 * 64];       // [k-pair][row-pair] A, 20 KB (max KC=40)
    __shared__ float4 Bs4[20 * 32];       // [k-pair][row-pair] B, 10 KB

    // ======================= Phase 1: GEMM =======================
    {
        if (bid == 0 && tid == 0) *out = 0.0f;   // published by the barrier fence

        const int tile = bid / KSPLIT;    // 0..19
        const int s    = bid % KSPLIT;    // k-slice
        int rem = tile, bm = 0;
        {
            const int cnt[4] = {8, 6, 4, 2};
            while (rem >= cnt[bm]) { rem -= cnt[bm]; bm++; }
        }
        const int bn = 2 * bm + rem;      // 64-col tile index, bn >= 2bm
        const int k0   = 72 * s;
        const int KC   = (s == 6) ? 40 : 36;   // two chunks per slice (72=2x36, 80=2x40)
        const int nkq  = KC >> 2;         // k-quads per chunk (9 or 10)
        const int nkp  = KC >> 1;         // k-pairs per chunk (18 or 20)

        const int tx = tid & 15;          // cols 4tx..4tx+3
        const int ty = tid >> 4;          // rows 8ty..8ty+7
        const int arow0 = bm * RT;
        const int brow0 = bn * CT;

        const int tsel = tid >> 7;        // 0: stage A, 1: stage B
        const int tid7 = tid & 127;

        ull acc2[8][4];
#pragma unroll
        for (int r = 0; r < 8; r++)
#pragma unroll
            for (int c = 0; c < 4; c++) acc2[r][c] = 0ull;

        for (int ch = 0; ch < 2; ch++) {
            const int kc0 = k0 + ch * KC;
            __syncthreads();              // previous chunk fully consumed
            if (tsel == 0) {
                // A: 64 row-pairs x nkq k-quads; kq fastest for coalescing
                for (int sl = tid7; sl < 64 * nkq; sl += 128) {
                    int rp = sl / nkq, kq = sl - rp * nkq;
                    const float* g = embs + (arow0 + 2 * rp) * DDIM + kc0 + 4 * kq;
                    float4 v0 = *(const float4*)g;
                    float4 v1 = *(const float4*)(g + DDIM);
                    As4[(2 * kq)     * 64 + rp] = make_float4(v0.x, v0.y, v1.x, v1.y);
                    As4[(2 * kq + 1) * 64 + rp] = make_float4(v0.z, v0.w, v1.z, v1.w);
                }
            } else {
                // B: 32 row-pairs x nkq k-quads
                for (int sl = tid7; sl < 32 * nkq; sl += 128) {
                    int rp = sl / nkq, kq = sl - rp * nkq;
                    const float* g = embs + (brow0 + 2 * rp) * DDIM + kc0 + 4 * kq;
                    float4 v0 = *(const float4*)g;
                    float4 v1 = *(const float4*)(g + DDIM);
                    Bs4[(2 * kq)     * 32 + rp] = make_float4(v0.x, v0.y, v1.x, v1.y);
                    Bs4[(2 * kq + 1) * 32 + rp] = make_float4(v0.z, v0.w, v1.z, v1.w);
                }
            }
            __syncthreads();

#pragma unroll 2
            for (int kp = 0; kp < nkp; kp++) {
                ull ar[8], bc[4];
#pragma unroll
                for (int i = 0; i < 4; i++) {
                    ulonglong2 u = *reinterpret_cast<const ulonglong2*>(
                        As4 + kp * 64 + 4 * ty + i);
                    ar[2 * i]     = u.x;  // row 8ty+2i   (k0,k1)
                    ar[2 * i + 1] = u.y;  // row 8ty+2i+1 (k0,k1)
                }
#pragma unroll
                for (int j = 0; j < 2; j++) {
                    ulonglong2 u = *reinterpret_cast<const ulonglong2*>(
                        Bs4 + kp * 32 + 2 * tx + j);
                    bc[2 * j]     = u.x;  // col 4tx+2j
                    bc[2 * j + 1] = u.y;  // col 4tx+2j+1
                }
#pragma unroll
                for (int r = 0; r < 8; r++)
#pragma unroll
                    for (int c = 0; c < 4; c++)
                        FMA_F32X2(acc2[r][c], ar[r], bc[c], acc2[r][c]);
            }
        }

        // Epilogue: unpack (k0+k1) and store; diagonal tiles emit diag partials.
        float* __restrict__ outp = g_part + s * (NROWS * NROWS);
        const int row0 = arow0 + 8 * ty;
        const int col0 = brow0 + 4 * tx;
        const bool hasdiag = (bn == 2 * bm) || (bn == 2 * bm + 1);
#pragma unroll
        for (int r = 0; r < 8; r++) {
            float sum[4];
#pragma unroll
            for (int c = 0; c < 4; c++) {
                float2 f = *(float2*)&acc2[r][c];
                sum[c] = f.x + f.y;
            }
            *(float4*)&outp[(row0 + r) * NROWS + col0] =
                make_float4(sum[0], sum[1], sum[2], sum[3]);
            if (hasdiag) {
                const int R = row0 + r;
#pragma unroll
                for (int c = 0; c < 4; c++)
                    if (R == col0 + c) g_diag[s][R] = sum[c];
            }
        }
    }

    // =================== Device-wide barrier ===================
    __syncthreads();
    __threadfence();                      // publish g_part / g_diag / *out
    if (tid == 0) {
        atomicAdd(&g_bar, 1);
        while (*(volatile int*)&g_bar < GRID) { }
    }
    __syncthreads();
    __threadfence();                      // acquire other blocks' writes

    // ======================= Phase 2: triplet =======================
    {
        const int w    = tid >> 5;        // warp 0..7
        const int lane = tid & 31;

        // Overlay tables onto the dead GEMM staging smem (As4 = 20 KB).
        float* const s_inv = (float*)As4;             // 512 floats (2 KB)
        int*   const s_cls = (int*)(s_inv + NROWS);   // 512 ints   (2 KB)
        float* const s_pos = (float*)(s_cls + NROWS); // 8 warps x 32 (1 KB)
        __shared__ float s_wsum[8];
        __shared__ int   fl;

        // Dtype probe (per-block): odd int32 positions within the first
        // 2048 bytes. int64 layout -> all zero high words; int32 -> ids.
        if (tid == 0) fl = 0;
        __syncthreads();
        if (((const int*)idxraw)[2 * tid + 1] != 0) atomicOr(&fl, 1);
        __syncthreads();
        const int is32 = fl;
        const int* __restrict__ i32 = (const int*)idxraw;
        const long long* __restrict__ i64 = (const long long*)idxraw;

#pragma unroll
        for (int e = 0; e < 2; e++) {
            int r = tid + e * 256;
            float d = 0.f;
#pragma unroll
            for (int p = 0; p < KSPLIT; p++) d += g_diag[p][r];   // coalesced
            s_inv[r] = 1.0f / fmaxf(sqrtf(d), 1e-8f);
            s_cls[r] = is32 ? i32[r] : (int)i64[r];
        }
        __syncthreads();

        float wsum = 0.f;
        const int slot = bid + GRID * w;  // warps 0..3 carry slots (560 >= 512)
        if (w < 4 && slot < 512) {
            const int i = (slot * 293) & 511;   // odd multiplier: bijection, balances load
            const int   ci   = s_cls[i];
            const float invi = s_inv[i];
            const int   rowbase = i * NROWS;

            // Phase A: batched partial-sum loads; no warp collectives here.
            float c[16];
#pragma unroll
            for (int sl = 0; sl < 16; sl++) {
                int j = i + 1 + lane + sl * 32;
                float sum = 0.f;
                if (j < NROWS) {
#pragma unroll
                    for (int p = 0; p < KSPLIT; p++)
                        sum += g_part[p * (NROWS * NROWS) + rowbase + j];
                    sum *= invi * s_inv[j];
                }
                c[sl] = sum;
            }

            // Phase B: uniform ballot compaction (all lanes hit every ballot).
            int np = 0;
#pragma unroll
            for (int sl = 0; sl < 16; sl++) {
                int j = i + 1 + lane + sl * 32;
                bool valid = (j < NROWS);
                bool match = valid && (s_cls[j] == ci);
                unsigned mask = __ballot_sync(0xffffffffu, match);
                if (match) {
                    int off = np + __popc(mask & ((1u << lane) - 1u));
                    if (off < 32) s_pos[w * 32 + off] = c[sl];
                }
                np += __popc(mask);
                c[sl] = (valid && !match) ? (c[sl] + 1.0f) : -1e30f;  // sentinel
            }
            if (np > 32) np = 32;         // capacity guard (expected np ~ 4)
            __syncwarp();

            // Hot loop: np broadcast-LDS reads, 16 unrolled register fmax each.
            float s0 = 0.f, s1 = 0.f;
            for (int p = 0; p < np; p++) {
                float bp = s_pos[w * 32 + p];
#pragma unroll
                for (int sl = 0; sl < 16; sl += 2) {
                    s0 += fmaxf(c[sl]     - bp, 0.0f);
                    s1 += fmaxf(c[sl + 1] - bp, 0.0f);
                }
            }
            wsum = s0 + s1;
        }

#pragma unroll
        for (int o = 16; o; o >>= 1) wsum += __shfl_xor_sync(0xffffffffu, wsum, o);
        if (lane == 0) s_wsum[w] = wsum;
        __syncthreads();
        if (tid < 8) {
            float v = s_wsum[tid];
#pragma unroll
            for (int o = 4; o; o >>= 1) v += __shfl_xor_sync(0xffu, v, o);
            if (tid == 0) atomicAdd(out, v);   // one atomic per block
        }
    }

    // ============ Reset counters for next graph replay ============
    __syncthreads();
    if (tid == 0) {
        int d = atomicAdd(&g_done, 1);
        if (d == GRID - 1) {
            g_bar  = 0;
            g_done = 0;
            __threadfence();
        }
    }
}

extern "C" void kernel_launch(void* const* d_in, const int* in_sizes, int n_in,
                              void* d_out, int out_size) {
    const float* embs = (const float*)d_in[0];
    const void*  indices = d_in[1];
    float* out = (float*)d_out;

    fused_kernel<<<GRID, 256>>>(embs, indices, out);
}